// round 8
// baseline (speedup 1.0000x reference)
#include <cuda_runtime.h>

namespace {

constexpr int THREADS = 160;   // 5 warps = 20 groups of 8 lanes
constexpr int NGRP = 20;
constexpr int MAXB = 2048;

__device__ __align__(16) float g_W1p[27 * 128];   // W1 transposed: [k][j]
__device__ __align__(16) float g_Wsum[9 * 128];   // W1p[d]+W1p[9+d]+W1p[18+d]
__device__ float4 g_zs[(size_t)MAXB * 81 * 32];   // z scratch: [b][c][j] j=h/4

__global__ void prep_kernel(const float* __restrict__ W1) {
    int j = threadIdx.x;  // 0..127
    #pragma unroll
    for (int k = 0; k < 27; k++) g_W1p[k * 128 + j] = W1[j * 27 + k];
    #pragma unroll
    for (int d = 0; d < 9; d++)
        g_Wsum[d * 128 + j] = W1[j * 27 + d] + W1[j * 27 + 9 + d] + W1[j * 27 + 18 + d];
}

__device__ __forceinline__ unsigned redux_maxu(unsigned v) {
    unsigned r; asm("redux.sync.max.u32 %0, %1, 0xffffffff;" : "=r"(r) : "r"(v)); return r;
}
__device__ __forceinline__ unsigned redux_minu(unsigned v) {
    unsigned r; asm("redux.sync.min.u32 %0, %1, 0xffffffff;" : "=r"(r) : "r"(v)); return r;
}

__global__ __launch_bounds__(THREADS, 8)
void sudoku_kernel(const float* __restrict__ x,
                   const float* __restrict__ W2,
                   float* __restrict__ out)
{
    __shared__ float4 w2s[288];           // W2 rows as float4
    __shared__ float cnt[3][9][9];
    __shared__ float score_s[96];         // 81 used; padding reads 0
    __shared__ int   pos_s[81];
    __shared__ unsigned char emptyb[81];
    __shared__ unsigned char empty0[81];

    const int tid  = threadIdx.x;
    const int lane = tid & 31;
    const int wid  = tid >> 5;
    const int grp  = tid >> 3;            // 0..19, 8-lane aligned groups
    const int gl   = tid & 7;             // lane within group: owns h[16gl..16gl+15]
    const long long b = blockIdx.x;
    const float* xb = x + b * 729;
    float* ob = out + b * 729;
    float4* zb = g_zs + (size_t)b * 81 * 32;

    for (int i = tid; i < 288; i += THREADS) w2s[i] = ((const float4*)W2)[i];
    for (int i = tid; i < 243; i += THREADS) (&cnt[0][0][0])[i] = 0.f;
    for (int i = tid; i < 729; i += THREADS) ob[i] = xb[i];   // x_pred init = x
    if (tid < 96) score_s[tid] = 0.f;
    __syncthreads();

    if (tid < 81) {
        int d = -1;
        #pragma unroll
        for (int e = 0; e < 9; e++)
            if (xb[tid * 9 + e] > 0.5f) d = e;
        pos_s[tid] = 0;
        if (d >= 0) {
            emptyb[tid] = 0; empty0[tid] = 0;
            int r = tid / 9, c = tid % 9, bx = (r / 3) * 3 + c / 3;
            atomicAdd(&cnt[0][r][d],  1.f);
            atomicAdd(&cnt[1][c][d],  1.f);
            atomicAdd(&cnt[2][bx][d], 1.f);
        } else {
            emptyb[tid] = 1; empty0[tid] = 1;
        }
    }
    __syncthreads();

    // relu in place, y = h @ W2^T slice, 3-round butterfly within 8-lane group:
    // afterwards every lane holds its group's full 9-vector p.
    auto reduce8 = [&](float4 z4[4], float p[9]) {
        #pragma unroll
        for (int k = 0; k < 4; k++) {
            z4[k].x = fmaxf(z4[k].x, 0.f); z4[k].y = fmaxf(z4[k].y, 0.f);
            z4[k].z = fmaxf(z4[k].z, 0.f); z4[k].w = fmaxf(z4[k].w, 0.f);
        }
        #pragma unroll
        for (int e = 0; e < 9; e++) {
            float4 w = w2s[e * 32 + gl * 4];
            float a = z4[0].x * w.x;
            a = fmaf(z4[0].y, w.y, a); a = fmaf(z4[0].z, w.z, a); a = fmaf(z4[0].w, w.w, a);
            #pragma unroll
            for (int k = 1; k < 4; k++) {
                float4 wk = w2s[e * 32 + gl * 4 + k];
                a = fmaf(z4[k].x, wk.x, a); a = fmaf(z4[k].y, wk.y, a);
                a = fmaf(z4[k].z, wk.z, a); a = fmaf(z4[k].w, wk.w, a);
            }
            p[e] = a;
        }
        #pragma unroll
        for (int off = 4; off > 0; off >>= 1) {
            #pragma unroll
            for (int e = 0; e < 9; e++)
                p[e] += __shfl_xor_sync(0xffffffffu, p[e], off);
        }
    };

    // score = max softmax prob, pos = first argmax
    auto scorepos = [&](const float p[9], float& sc, int& bp) {
        float mx = p[0];
        #pragma unroll
        for (int e = 1; e < 9; e++) mx = fmaxf(mx, p[e]);
        float sum = 0.f, best = -1.f; bp = 0;
        #pragma unroll
        for (int e = 0; e < 9; e++) {
            float q = expf(p[e] - mx);
            sum += q;
            if (q > best) { best = q; bp = e; }
        }
        sc = best / sum;
    };

    auto map_cell = [](int i, int rm, int cm3, int brm) -> int {
        if (i < 3)  return 3 * rm + i;
        if (i < 12) return 27 + 3 * (i - 3) + cm3;
        return 54 + 3 * (brm + (i - 12)) + cm3;
    };

    // ---- Initial pass: one 8-lane group per cell, per type region ----
    // rows 0..26
    for (int base = 0; base < 27; base += NGRP) {
        int c = base + grp; bool valid = (c < 27);
        int cc = valid ? c : 0;
        const float* f = cnt[0][cc / 3];
        float4 z4[4] = {};
        #pragma unroll
        for (int e = 0; e < 9; e++) {
            float fv = f[e];
            #pragma unroll
            for (int k = 0; k < 4; k++) {
                float4 w = __ldg((const float4*)(g_Wsum + e * 128) + gl * 4 + k);
                z4[k].x = fmaf(fv, w.x, z4[k].x); z4[k].y = fmaf(fv, w.y, z4[k].y);
                z4[k].z = fmaf(fv, w.z, z4[k].z); z4[k].w = fmaf(fv, w.w, z4[k].w);
            }
        }
        if (valid) {
            #pragma unroll
            for (int k = 0; k < 4; k++) zb[cc * 32 + gl * 4 + k] = z4[k];
        }
        float p[9]; reduce8(z4, p);
        float sc; int bp; scorepos(p, sc, bp);
        if (valid && emptyb[cc] && gl == 0) { score_s[cc] = sc; pos_s[cc] = bp; }
    }
    // cols 27..53
    for (int base = 0; base < 27; base += NGRP) {
        int c = base + grp; bool valid = (c < 27);
        int cc = valid ? c : 0;
        int g0 = 3 * (cc % 3);
        float4 z4[4] = {};
        #pragma unroll
        for (int blk = 0; blk < 3; blk++) {
            const float* f = cnt[1][g0 + blk];
            #pragma unroll
            for (int e = 0; e < 9; e++) {
                float fv = f[e];
                #pragma unroll
                for (int k = 0; k < 4; k++) {
                    float4 w = __ldg((const float4*)(g_W1p + (9 * blk + e) * 128) + gl * 4 + k);
                    z4[k].x = fmaf(fv, w.x, z4[k].x); z4[k].y = fmaf(fv, w.y, z4[k].y);
                    z4[k].z = fmaf(fv, w.z, z4[k].z); z4[k].w = fmaf(fv, w.w, z4[k].w);
                }
            }
        }
        int co = cc + 27;
        if (valid) {
            #pragma unroll
            for (int k = 0; k < 4; k++) zb[co * 32 + gl * 4 + k] = z4[k];
        }
        float p[9]; reduce8(z4, p);
        float sc; int bp; scorepos(p, sc, bp);
        if (valid && emptyb[co] && gl == 0) { score_s[co] = sc; pos_s[co] = bp; }
    }
    // boxes 54..80
    for (int base = 0; base < 27; base += NGRP) {
        int c = base + grp; bool valid = (c < 27);
        int cc = valid ? c : 0;
        const float* f = cnt[2][3 * (cc / 9) + cc % 3];
        float4 z4[4] = {};
        #pragma unroll
        for (int e = 0; e < 9; e++) {
            float fv = f[e];
            #pragma unroll
            for (int k = 0; k < 4; k++) {
                float4 w = __ldg((const float4*)(g_Wsum + e * 128) + gl * 4 + k);
                z4[k].x = fmaf(fv, w.x, z4[k].x); z4[k].y = fmaf(fv, w.y, z4[k].y);
                z4[k].z = fmaf(fv, w.z, z4[k].z); z4[k].w = fmaf(fv, w.w, z4[k].w);
            }
        }
        int co = cc + 54;
        if (valid) {
            #pragma unroll
            for (int k = 0; k < 4; k++) zb[co * 32 + gl * 4 + k] = z4[k];
        }
        float p[9]; reduce8(z4, p);
        float sc; int bp; scorepos(p, sc, bp);
        if (valid && emptyb[co] && gl == 0) { score_s[co] = sc; pos_s[co] = bp; }
    }

    // ---- Sequential fill loop ----
    for (int iter = 0; iter < 81; ++iter) {
        __syncthreads();   // A: prior-iter writes visible block-wide

        float s0 = score_s[lane];
        float s1 = score_s[lane + 32];
        float s2 = score_s[lane + 64];
        unsigned bb = __float_as_uint(s0); int bi = lane;
        unsigned v1 = __float_as_uint(s1); if (v1 > bb) { bb = v1; bi = lane + 32; }
        unsigned v2 = __float_as_uint(s2); if (v2 > bb) { bb = v2; bi = lane + 64; }
        unsigned wmax = redux_maxu(bb);
        if (wmax == 0u) break;              // uniform across block
        unsigned cand = (bb == wmax) ? (unsigned)bi : 0xFFu;
        const int m = (int)redux_minu(cand);
        const int d = pos_s[m];

        const int rm = m / 9, cm = m % 9;
        const int cm3 = cm / 3, brm = (rm / 3) * 3;

        int cl = map_cell(lane < 15 ? lane : 0, rm, cm3, brm);
        bool pr = (lane < 15) && (cl != m) && emptyb[cl];
        unsigned mask = __ballot_sync(0xffffffffu, pr);
        int nempty = __popc(mask);          // <= 14 < NGRP: single pass

        float sc = 0.f; int bp = 0, c = 0; bool active = false;
        if (4 * wid < nempty) {             // warp has >=1 active group
            active = (grp < nempty);
            int bit = active ? (int)__fns(mask, 0, grp + 1) : 0;
            c = map_cell(bit, rm, cm3, brm);
            const float* wrow = (bit >= 3 && bit < 12)
                              ? g_W1p + (9 * (cm % 3) + d) * 128
                              : g_Wsum + d * 128;
            float4 z4[4];
            #pragma unroll
            for (int k = 0; k < 4; k++) {
                float4 z = zb[c * 32 + gl * 4 + k];
                float4 w = __ldg((const float4*)wrow + gl * 4 + k);
                z.x += w.x; z.y += w.y; z.z += w.z; z.w += w.w;
                z4[k] = z;
            }
            if (active) {
                #pragma unroll
                for (int k = 0; k < 4; k++) zb[c * 32 + gl * 4 + k] = z4[k];
            }
            float p[9]; reduce8(z4, p);
            scorepos(p, sc, bp);
        }

        __syncthreads();   // B: all selection/mask/z reads done before state writes
        if (tid == 0) { emptyb[m] = 0; score_s[m] = 0.f; }
        if (active && gl == 0) { score_s[c] = sc; pos_s[c] = bp; }
    }
    __syncthreads();

    // ---- Final pass: softmax of frozen z for initially-empty cells ----
    for (int base = 0; base < 81; base += NGRP) {
        int c = base + grp;
        int cc = (c < 81) ? c : 0;
        float4 z4[4];
        #pragma unroll
        for (int k = 0; k < 4; k++) z4[k] = zb[cc * 32 + gl * 4 + k];
        float p[9]; reduce8(z4, p);
        float mx = p[0];
        #pragma unroll
        for (int e = 1; e < 9; e++) mx = fmaxf(mx, p[e]);
        float sum = 0.f;
        #pragma unroll
        for (int e = 0; e < 9; e++) { p[e] = expf(p[e] - mx); sum += p[e]; }
        if (c < 81 && empty0[cc]) {
            ob[cc * 9 + gl] = p[gl] / sum;
            if (gl == 0) ob[cc * 9 + 8] = p[8] / sum;
        }
    }
}

} // namespace

extern "C" void kernel_launch(void* const* d_in, const int* in_sizes, int n_in,
                              void* d_out, int out_size) {
    const float* x  = (const float*)d_in[0];
    const float* W1 = (const float*)d_in[1];
    const float* W2 = (const float*)d_in[2];
    float* out = (float*)d_out;
    int B = in_sizes[0] / 729;
    prep_kernel<<<1, 128>>>(W1);
    sudoku_kernel<<<B, THREADS>>>(x, W2, out);
}

// round 9
// speedup vs baseline: 2.6087x; 2.6087x over previous
#include <cuda_runtime.h>

namespace {

constexpr int MAXB = 2048;

__device__ __align__(16) float g_W1p[27 * 128];   // W1 transposed: [k][j]
__device__ __align__(16) float g_Wsum[9 * 128];   // W1p[d]+W1p[9+d]+W1p[18+d]
__device__ float4 g_zs[(size_t)MAXB * 81 * 32];   // z scratch: [b][c][lane]

__global__ void prep_kernel(const float* __restrict__ W1) {
    int j = threadIdx.x;  // 0..127
    #pragma unroll
    for (int k = 0; k < 27; k++) g_W1p[k * 128 + j] = W1[j * 27 + k];
    #pragma unroll
    for (int d = 0; d < 9; d++)
        g_Wsum[d * 128 + j] = W1[j * 27 + d] + W1[j * 27 + 9 + d] + W1[j * 27 + 18 + d];
}

__device__ __forceinline__ unsigned redux_maxu(unsigned v) {
    unsigned r; asm("redux.sync.max.u32 %0, %1, 0xffffffff;" : "=r"(r) : "r"(v)); return r;
}
__device__ __forceinline__ unsigned redux_minu(unsigned v) {
    unsigned r; asm("redux.sync.min.u32 %0, %1, 0xffffffff;" : "=r"(r) : "r"(v)); return r;
}

// ONE WARP PER BOARD. 32-thread CTAs; all state warp-private; no block barriers.
__global__ __launch_bounds__(32)
void sudoku_kernel(const float* __restrict__ x,
                   const float* __restrict__ W2,
                   float* __restrict__ out)
{
    __shared__ float cnt[3][9][9];
    __shared__ float score_s[96];         // 81 used; padding reads 0
    __shared__ int   pos_s[81];
    __shared__ unsigned char emptyb[81];
    __shared__ unsigned char empty0[81];

    const int lane = threadIdx.x;
    const long long b = blockIdx.x;
    const float* xb = x + b * 729;
    float* ob = out + b * 729;
    float4* zb = g_zs + (size_t)b * 81 * 32;

    // W2 resident in registers: lane owns hidden units 4*lane..4*lane+3
    float4 w2r[9];
    #pragma unroll
    for (int e = 0; e < 9; e++)
        w2r[e] = __ldg((const float4*)(W2 + e * 128) + lane);

    for (int i = lane; i < 243; i += 32) (&cnt[0][0][0])[i] = 0.f;
    for (int i = lane; i < 729; i += 32) ob[i] = xb[i];   // x_pred init = x
    for (int i = lane; i < 96; i += 32) score_s[i] = 0.f;
    __syncwarp();

    for (int c = lane; c < 81; c += 32) {
        int d = -1;
        #pragma unroll
        for (int e = 0; e < 9; e++)
            if (xb[c * 9 + e] > 0.5f) d = e;
        pos_s[c] = 0;
        if (d >= 0) {
            emptyb[c] = 0; empty0[c] = 0;
            int r = c / 9, cc = c % 9, bx = (r / 3) * 3 + cc / 3;
            atomicAdd(&cnt[0][r][d],  1.f);
            atomicAdd(&cnt[1][cc][d], 1.f);
            atomicAdd(&cnt[2][bx][d], 1.f);
        } else {
            emptyb[c] = 1; empty0[c] = 1;
        }
    }
    __syncwarp();

    // relu(z) @ W2^T + full-warp XOR butterfly: every lane gets the 9-vector p.
    auto reduce_p = [&](float4 z, float p[9]) {
        float h0 = fmaxf(z.x, 0.f), h1 = fmaxf(z.y, 0.f);
        float h2 = fmaxf(z.z, 0.f), h3 = fmaxf(z.w, 0.f);
        #pragma unroll
        for (int e = 0; e < 9; e++) {
            float a = h0 * w2r[e].x;
            a = fmaf(h1, w2r[e].y, a);
            a = fmaf(h2, w2r[e].z, a);
            a = fmaf(h3, w2r[e].w, a);
            p[e] = a;
        }
        #pragma unroll
        for (int off = 16; off > 0; off >>= 1) {
            #pragma unroll
            for (int e = 0; e < 9; e++)
                p[e] += __shfl_xor_sync(0xffffffffu, p[e], off);
        }
    };

    // score = max softmax prob (fast exp/div), pos = first argmax
    auto scorepos = [&](int c, const float p[9]) {
        float mx = p[0];
        #pragma unroll
        for (int e = 1; e < 9; e++) mx = fmaxf(mx, p[e]);
        float sum = 0.f, best = -1.f; int bp = 0;
        #pragma unroll
        for (int e = 0; e < 9; e++) {
            float q = __expf(p[e] - mx);
            sum += q;
            if (q > best) { best = q; bp = e; }
        }
        if (lane == 0) { score_s[c] = __fdividef(best, sum); pos_s[c] = bp; }
    };

    auto map_cell = [](int i, int rm, int cm3, int brm) -> int {
        if (i < 3)  return 3 * rm + i;
        if (i < 12) return 27 + 3 * (i - 3) + cm3;
        return 54 + 3 * (brm + (i - 12)) + cm3;
    };

    // ---- Initial pass: fresh z for every empty cell (serial over cells) ----
    for (int c = 0; c < 81; c++) {
        if (!emptyb[c]) continue;
        float4 z = make_float4(0.f, 0.f, 0.f, 0.f);
        if (c < 27) {
            const float* f = cnt[0][c / 3];
            #pragma unroll
            for (int e = 0; e < 9; e++) {
                float fv = f[e];
                float4 w = __ldg((const float4*)(g_Wsum + e * 128) + lane);
                z.x = fmaf(fv, w.x, z.x); z.y = fmaf(fv, w.y, z.y);
                z.z = fmaf(fv, w.z, z.z); z.w = fmaf(fv, w.w, z.w);
            }
        } else if (c < 54) {
            int g0 = 3 * ((c - 27) % 3);
            #pragma unroll
            for (int blk = 0; blk < 3; blk++) {
                const float* f = cnt[1][g0 + blk];
                #pragma unroll
                for (int e = 0; e < 9; e++) {
                    float fv = f[e];
                    float4 w = __ldg((const float4*)(g_W1p + (9 * blk + e) * 128) + lane);
                    z.x = fmaf(fv, w.x, z.x); z.y = fmaf(fv, w.y, z.y);
                    z.z = fmaf(fv, w.z, z.z); z.w = fmaf(fv, w.w, z.w);
                }
            }
        } else {
            int u = c - 54;
            const float* f = cnt[2][3 * (u / 9) + u % 3];
            #pragma unroll
            for (int e = 0; e < 9; e++) {
                float fv = f[e];
                float4 w = __ldg((const float4*)(g_Wsum + e * 128) + lane);
                z.x = fmaf(fv, w.x, z.x); z.y = fmaf(fv, w.y, z.y);
                z.z = fmaf(fv, w.z, z.z); z.w = fmaf(fv, w.w, z.w);
            }
        }
        zb[c * 32 + lane] = z;
        float p[9];
        reduce_p(z, p);
        scorepos(c, p);
    }
    __syncwarp();

    // ---- Sequential fill loop (warp-private; ~45 iterations) ----
    for (int iter = 0; iter < 81; ++iter) {
        __syncwarp();   // make lane-0 smem writes from prior iter visible

        float s0 = score_s[lane];
        float s1 = score_s[lane + 32];
        float s2 = score_s[lane + 64];
        unsigned bb = __float_as_uint(s0); int bi = lane;
        unsigned v1 = __float_as_uint(s1); if (v1 > bb) { bb = v1; bi = lane + 32; }
        unsigned v2 = __float_as_uint(s2); if (v2 > bb) { bb = v2; bi = lane + 64; }
        unsigned wmax = redux_maxu(bb);
        if (wmax == 0u) break;              // board solved
        unsigned cand = (bb == wmax) ? (unsigned)bi : 0xFFu;
        const int m = (int)redux_minu(cand);   // first-max index
        const int d = pos_s[m];

        const int rm = m / 9, cm = m % 9;
        const int cm3 = cm / 3, brm = (rm / 3) * 3;

        int cl = map_cell(lane < 15 ? lane : 0, rm, cm3, brm);
        bool pr = (lane < 15) && (cl != m) && emptyb[cl];
        unsigned mask = __ballot_sync(0xffffffffu, pr);
        int ne = __popc(mask);

        const float4 wsum4 = __ldg((const float4*)(g_Wsum + d * 128) + lane);
        const float4 wcol4 = __ldg((const float4*)(g_W1p + (9 * (cm % 3) + d) * 128) + lane);

        if (lane == 0) { emptyb[m] = 0; score_s[m] = 0.f; }  // no reads until next syncwarp

        // serial cells, software-pipelined z prefetch
        int bit = 0, c = 0; float4 z;
        if (ne > 0) {
            bit = (int)__fns(mask, 0, 1);
            c = map_cell(bit, rm, cm3, brm);
            z = zb[c * 32 + lane];
        }
        for (int idx = 0; idx < ne; idx++) {
            int nbit = 0, nc = 0; float4 zn;
            if (idx + 1 < ne) {
                nbit = (int)__fns(mask, 0, idx + 2);
                nc = map_cell(nbit, rm, cm3, brm);
                zn = zb[nc * 32 + lane];           // prefetch next cell's z
            }
            float4 w = (bit >= 3 && bit < 12) ? wcol4 : wsum4;
            z.x += w.x; z.y += w.y; z.z += w.z; z.w += w.w;
            zb[c * 32 + lane] = z;
            float p[9];
            reduce_p(z, p);
            scorepos(c, p);
            bit = nbit; c = nc; z = zn;
        }
    }
    __syncwarp();

    // ---- Final pass: softmax of frozen z for initially-empty cells ----
    for (int c = 0; c < 81; c++) {
        if (!empty0[c]) continue;
        float4 z = zb[c * 32 + lane];
        float p[9];
        reduce_p(z, p);
        float mx = p[0];
        #pragma unroll
        for (int e = 1; e < 9; e++) mx = fmaxf(mx, p[e]);
        float sum = 0.f;
        #pragma unroll
        for (int e = 0; e < 9; e++) { p[e] = __expf(p[e] - mx); sum += p[e]; }
        if (lane < 9) ob[c * 9 + lane] = __fdividef(p[lane], sum);
    }
}

} // namespace

extern "C" void kernel_launch(void* const* d_in, const int* in_sizes, int n_in,
                              void* d_out, int out_size) {
    const float* x  = (const float*)d_in[0];
    const float* W1 = (const float*)d_in[1];
    const float* W2 = (const float*)d_in[2];
    float* out = (float*)d_out;
    int B = in_sizes[0] / 729;
    prep_kernel<<<1, 128>>>(W1);
    sudoku_kernel<<<B, 32>>>(x, W2, out);
}

// round 10
// speedup vs baseline: 2.6351x; 1.0101x over previous
#include <cuda_runtime.h>

namespace {

constexpr int MAXB = 2048;
constexpr int NWB  = 4;     // warps per board
constexpr int THREADS = 32 * NWB;

__device__ __align__(16) float g_W1p[27 * 128];   // W1 transposed: [k][j]
__device__ __align__(16) float g_Wsum[9 * 128];   // W1p[d]+W1p[9+d]+W1p[18+d]
__device__ float4 g_zs[(size_t)MAXB * 81 * 32];   // z scratch: [b][c][lane]

__global__ void prep_kernel(const float* __restrict__ W1) {
    int j = threadIdx.x;  // 0..127
    #pragma unroll
    for (int k = 0; k < 27; k++) g_W1p[k * 128 + j] = W1[j * 27 + k];
    #pragma unroll
    for (int d = 0; d < 9; d++)
        g_Wsum[d * 128 + j] = W1[j * 27 + d] + W1[j * 27 + 9 + d] + W1[j * 27 + 18 + d];
}

__device__ __forceinline__ unsigned redux_maxu(unsigned v) {
    unsigned r; asm("redux.sync.max.u32 %0, %1, 0xffffffff;" : "=r"(r) : "r"(v)); return r;
}
__device__ __forceinline__ unsigned redux_minu(unsigned v) {
    unsigned r; asm("redux.sync.min.u32 %0, %1, 0xffffffff;" : "=r"(r) : "r"(v)); return r;
}

__global__ __launch_bounds__(THREADS)
void sudoku_kernel(const float* __restrict__ x,
                   const float* __restrict__ W2,
                   float* __restrict__ out)
{
    __shared__ float cnt[3][9][9];
    __shared__ float score_s[96];         // 81 used; padding reads 0
    __shared__ int   pos_s[81];
    __shared__ unsigned char emptyb[81];
    __shared__ unsigned char empty0[81];

    const int tid  = threadIdx.x;
    const int lane = tid & 31;
    const int wid  = tid >> 5;
    const long long b = blockIdx.x;
    const float* xb = x + b * 729;
    float* ob = out + b * 729;
    float4* zb = g_zs + (size_t)b * 81 * 32;

    // W2 resident in registers: lane owns hidden units 4*lane..4*lane+3
    float4 w2r[9];
    #pragma unroll
    for (int e = 0; e < 9; e++)
        w2r[e] = __ldg((const float4*)(W2 + e * 128) + lane);

    for (int i = tid; i < 243; i += THREADS) (&cnt[0][0][0])[i] = 0.f;
    for (int i = tid; i < 729; i += THREADS) ob[i] = xb[i];   // x_pred init = x
    if (tid < 96) score_s[tid] = 0.f;
    __syncthreads();

    if (tid < 81) {
        int d = -1;
        #pragma unroll
        for (int e = 0; e < 9; e++)
            if (xb[tid * 9 + e] > 0.5f) d = e;
        pos_s[tid] = 0;
        if (d >= 0) {
            emptyb[tid] = 0; empty0[tid] = 0;
            int r = tid / 9, cc = tid % 9, bx = (r / 3) * 3 + cc / 3;
            atomicAdd(&cnt[0][r][d],  1.f);
            atomicAdd(&cnt[1][cc][d], 1.f);
            atomicAdd(&cnt[2][bx][d], 1.f);
        } else {
            emptyb[tid] = 1; empty0[tid] = 1;
        }
    }
    __syncthreads();

    // relu(z) @ W2^T + full-warp XOR butterfly: every lane gets the 9-vector p.
    auto reduce_p = [&](float4 z, float p[9]) {
        float h0 = fmaxf(z.x, 0.f), h1 = fmaxf(z.y, 0.f);
        float h2 = fmaxf(z.z, 0.f), h3 = fmaxf(z.w, 0.f);
        #pragma unroll
        for (int e = 0; e < 9; e++) {
            float a = h0 * w2r[e].x;
            a = fmaf(h1, w2r[e].y, a);
            a = fmaf(h2, w2r[e].z, a);
            a = fmaf(h3, w2r[e].w, a);
            p[e] = a;
        }
        #pragma unroll
        for (int off = 16; off > 0; off >>= 1) {
            #pragma unroll
            for (int e = 0; e < 9; e++)
                p[e] += __shfl_xor_sync(0xffffffffu, p[e], off);
        }
    };

    // score = max softmax prob (fast exp/div), pos = first argmax
    auto scorepos = [&](int c, const float p[9]) {
        float mx = p[0];
        #pragma unroll
        for (int e = 1; e < 9; e++) mx = fmaxf(mx, p[e]);
        float sum = 0.f, best = -1.f; int bp = 0;
        #pragma unroll
        for (int e = 0; e < 9; e++) {
            float q = __expf(p[e] - mx);
            sum += q;
            if (q > best) { best = q; bp = e; }
        }
        if (lane == 0) { score_s[c] = __fdividef(best, sum); pos_s[c] = bp; }
    };

    auto map_cell = [](int i, int rm, int cm3, int brm) -> int {
        if (i < 3)  return 3 * rm + i;
        if (i < 12) return 27 + 3 * (i - 3) + cm3;
        return 54 + 3 * (brm + (i - 12)) + cm3;
    };

    // ---- Initial pass: fresh z for every empty cell (cells split over warps) ----
    for (int c = wid; c < 81; c += NWB) {
        if (!emptyb[c]) continue;
        float4 z = make_float4(0.f, 0.f, 0.f, 0.f);
        if (c < 27) {
            const float* f = cnt[0][c / 3];
            #pragma unroll
            for (int e = 0; e < 9; e++) {
                float fv = f[e];
                float4 w = __ldg((const float4*)(g_Wsum + e * 128) + lane);
                z.x = fmaf(fv, w.x, z.x); z.y = fmaf(fv, w.y, z.y);
                z.z = fmaf(fv, w.z, z.z); z.w = fmaf(fv, w.w, z.w);
            }
        } else if (c < 54) {
            int g0 = 3 * ((c - 27) % 3);
            #pragma unroll
            for (int blk = 0; blk < 3; blk++) {
                const float* f = cnt[1][g0 + blk];
                #pragma unroll
                for (int e = 0; e < 9; e++) {
                    float fv = f[e];
                    float4 w = __ldg((const float4*)(g_W1p + (9 * blk + e) * 128) + lane);
                    z.x = fmaf(fv, w.x, z.x); z.y = fmaf(fv, w.y, z.y);
                    z.z = fmaf(fv, w.z, z.z); z.w = fmaf(fv, w.w, z.w);
                }
            }
        } else {
            int u = c - 54;
            const float* f = cnt[2][3 * (u / 9) + u % 3];
            #pragma unroll
            for (int e = 0; e < 9; e++) {
                float fv = f[e];
                float4 w = __ldg((const float4*)(g_Wsum + e * 128) + lane);
                z.x = fmaf(fv, w.x, z.x); z.y = fmaf(fv, w.y, z.y);
                z.z = fmaf(fv, w.z, z.z); z.w = fmaf(fv, w.w, z.w);
            }
        }
        zb[c * 32 + lane] = z;
        float p[9];
        reduce_p(z, p);
        scorepos(c, p);
    }
    __syncthreads();

    // ---- Sequential fill loop: ONE barrier per iteration ----
    // Each warp redundantly computes selection (identical inputs -> identical m,d).
    for (int iter = 0; iter < 81; ++iter) {
        float s0 = score_s[lane];
        float s1 = score_s[lane + 32];
        float s2 = score_s[lane + 64];
        unsigned bb = __float_as_uint(s0); int bi = lane;
        unsigned v1 = __float_as_uint(s1); if (v1 > bb) { bb = v1; bi = lane + 32; }
        unsigned v2 = __float_as_uint(s2); if (v2 > bb) { bb = v2; bi = lane + 64; }
        unsigned wmax = redux_maxu(bb);
        if (wmax == 0u) break;              // CTA-uniform: all warps break together
        unsigned cand = (bb == wmax) ? (unsigned)bi : 0xFFu;
        const int m = (int)redux_minu(cand);   // first-max index
        const int d = pos_s[m];

        const int rm = m / 9, cm = m % 9;
        const int cm3 = cm / 3, brm = (rm / 3) * 3;

        // ballot over affected cells (benign race on emptyb[m]: excluded via cl!=m)
        int cl = map_cell(lane < 15 ? lane : 0, rm, cm3, brm);
        bool pr = (lane < 15) && (cl != m) && emptyb[cl];
        unsigned mask = __ballot_sync(0xffffffffu, pr);
        int ne = __popc(mask);

        if (tid == 0) { emptyb[m] = 0; score_s[m] = 0.f; }  // read after next barrier only

        const float4 wsum4 = __ldg((const float4*)(g_Wsum + d * 128) + lane);
        const float4 wcol4 = __ldg((const float4*)(g_W1p + (9 * (cm % 3) + d) * 128) + lane);

        // warp wid takes cells idx = wid, wid+NWB, ... (disjoint across warps)
        for (int idx = wid; idx < ne; idx += NWB) {
            int bit = (int)__fns(mask, 0, idx + 1);
            int c   = map_cell(bit, rm, cm3, brm);
            float4 w = (bit >= 3 && bit < 12) ? wcol4 : wsum4;
            float4 z = zb[c * 32 + lane];
            z.x += w.x; z.y += w.y; z.z += w.z; z.w += w.w;
            zb[c * 32 + lane] = z;
            float p[9];
            reduce_p(z, p);
            scorepos(c, p);
        }

        __syncthreads();   // publish z/score/pos writes + m-clears to all warps
    }
    __syncthreads();

    // ---- Final pass: softmax of frozen z for initially-empty cells ----
    for (int c = wid; c < 81; c += NWB) {
        if (!empty0[c]) continue;
        float4 z = zb[c * 32 + lane];
        float p[9];
        reduce_p(z, p);
        float mx = p[0];
        #pragma unroll
        for (int e = 1; e < 9; e++) mx = fmaxf(mx, p[e]);
        float sum = 0.f;
        #pragma unroll
        for (int e = 0; e < 9; e++) { p[e] = __expf(p[e] - mx); sum += p[e]; }
        if (lane < 9) ob[c * 9 + lane] = __fdividef(p[lane], sum);
    }
}

} // namespace

extern "C" void kernel_launch(void* const* d_in, const int* in_sizes, int n_in,
                              void* d_out, int out_size) {
    const float* x  = (const float*)d_in[0];
    const float* W1 = (const float*)d_in[1];
    const float* W2 = (const float*)d_in[2];
    float* out = (float*)d_out;
    int B = in_sizes[0] / 729;
    prep_kernel<<<1, 128>>>(W1);
    sudoku_kernel<<<B, THREADS>>>(x, W2, out);
}

// round 11
// speedup vs baseline: 3.6263x; 1.3761x over previous
#include <cuda_runtime.h>

namespace {

constexpr int MAXB = 2048;
constexpr int THREADS = 128;   // 4 warps = 16 groups of 8 lanes

__device__ __align__(16) float g_W1p[27 * 128];   // W1 transposed: [k][j]
__device__ __align__(16) float g_Wsum[9 * 128];   // W1p[d]+W1p[9+d]+W1p[18+d]
__device__ float4 g_zs[(size_t)MAXB * 81 * 32];   // z scratch: [b][c][j]

__global__ void prep_kernel(const float* __restrict__ W1) {
    int j = threadIdx.x;  // 0..127
    #pragma unroll
    for (int k = 0; k < 27; k++) g_W1p[k * 128 + j] = W1[j * 27 + k];
    #pragma unroll
    for (int d = 0; d < 9; d++)
        g_Wsum[d * 128 + j] = W1[j * 27 + d] + W1[j * 27 + 9 + d] + W1[j * 27 + 18 + d];
}

__device__ __forceinline__ unsigned redux_maxu(unsigned v) {
    unsigned r; asm("redux.sync.max.u32 %0, %1, 0xffffffff;" : "=r"(r) : "r"(v)); return r;
}
__device__ __forceinline__ unsigned redux_minu(unsigned v) {
    unsigned r; asm("redux.sync.min.u32 %0, %1, 0xffffffff;" : "=r"(r) : "r"(v)); return r;
}

__global__ __launch_bounds__(THREADS)
void sudoku_kernel(const float* __restrict__ x,
                   const float* __restrict__ W2,
                   float* __restrict__ out)
{
    __shared__ float4 w2s[288];           // W2 as float4: w2s[e*32+j]
    __shared__ float cnt[3][9][9];
    __shared__ float score_s[96];         // 81 used; padding reads 0
    __shared__ int   pos_s[81];
    __shared__ unsigned char emptyb[81];
    __shared__ unsigned char empty0[81];

    const int tid  = threadIdx.x;
    const int lane = tid & 31;
    const int wid  = tid >> 5;
    const int grp  = tid >> 3;            // 0..15
    const int gl   = tid & 7;             // lane-in-group; owns float4s k*8+gl, k=0..3
    const unsigned gmask = 0xFFu << (lane & 24);   // this group's 8 lanes
    const long long b = blockIdx.x;
    const float* xb = x + b * 729;
    float* ob = out + b * 729;
    float4* zb = g_zs + (size_t)b * 81 * 32;

    for (int i = tid; i < 288; i += THREADS) w2s[i] = ((const float4*)W2)[i];
    for (int i = tid; i < 243; i += THREADS) (&cnt[0][0][0])[i] = 0.f;
    for (int i = tid; i < 729; i += THREADS) ob[i] = xb[i];   // x_pred init = x
    if (tid < 96) score_s[tid] = 0.f;
    __syncthreads();

    if (tid < 81) {
        int d = -1;
        #pragma unroll
        for (int e = 0; e < 9; e++)
            if (xb[tid * 9 + e] > 0.5f) d = e;
        pos_s[tid] = 0;
        if (d >= 0) {
            emptyb[tid] = 0; empty0[tid] = 0;
            int r = tid / 9, cc = tid % 9, bx = (r / 3) * 3 + cc / 3;
            atomicAdd(&cnt[0][r][d],  1.f);
            atomicAdd(&cnt[1][cc][d], 1.f);
            atomicAdd(&cnt[2][bx][d], 1.f);
        } else {
            emptyb[tid] = 1; empty0[tid] = 1;
        }
    }
    __syncthreads();

    // relu + y = h @ W2^T (this lane's 16 h-units) + 3-round group butterfly:
    // every lane of the group ends with the full 9-vector p for its group's cell.
    auto reduce8 = [&](float4 z4[4], float p[9]) {
        #pragma unroll
        for (int k = 0; k < 4; k++) {
            z4[k].x = fmaxf(z4[k].x, 0.f); z4[k].y = fmaxf(z4[k].y, 0.f);
            z4[k].z = fmaxf(z4[k].z, 0.f); z4[k].w = fmaxf(z4[k].w, 0.f);
        }
        #pragma unroll
        for (int e = 0; e < 9; e++) {
            float a = 0.f;
            #pragma unroll
            for (int k = 0; k < 4; k++) {
                float4 w = w2s[e * 32 + k * 8 + gl];
                a = fmaf(z4[k].x, w.x, a); a = fmaf(z4[k].y, w.y, a);
                a = fmaf(z4[k].z, w.z, a); a = fmaf(z4[k].w, w.w, a);
            }
            p[e] = a;
        }
        #pragma unroll
        for (int off = 4; off > 0; off >>= 1) {
            #pragma unroll
            for (int e = 0; e < 9; e++)
                p[e] += __shfl_xor_sync(gmask, p[e], off);
        }
    };

    auto scorepos8 = [&](int c, const float p[9]) {
        float mx = p[0];
        #pragma unroll
        for (int e = 1; e < 9; e++) mx = fmaxf(mx, p[e]);
        float sum = 0.f, best = -1.f; int bp = 0;
        #pragma unroll
        for (int e = 0; e < 9; e++) {
            float q = __expf(p[e] - mx);
            sum += q;
            if (q > best) { best = q; bp = e; }
        }
        if (gl == 0) { score_s[c] = __fdividef(best, sum); pos_s[c] = bp; }
    };

    auto map_cell = [](int i, int rm, int cm3, int brm) -> int {
        if (i < 3)  return 3 * rm + i;
        if (i < 12) return 27 + 3 * (i - 3) + cm3;
        return 54 + 3 * (brm + (i - 12)) + cm3;
    };

    // ---- Initial pass: 16 groups over each 27-cell type region ----
    // rows 0..26 (3x-replicated f -> Wsum)
    for (int base = 0; base < 27; base += 16) {
        int cc = base + grp;
        if (cc < 27 && emptyb[cc]) {
            const float* f = cnt[0][cc / 3];
            float4 z4[4] = {};
            #pragma unroll
            for (int e = 0; e < 9; e++) {
                float fv = f[e];
                #pragma unroll
                for (int k = 0; k < 4; k++) {
                    float4 w = __ldg((const float4*)(g_Wsum + e * 128) + k * 8 + gl);
                    z4[k].x = fmaf(fv, w.x, z4[k].x); z4[k].y = fmaf(fv, w.y, z4[k].y);
                    z4[k].z = fmaf(fv, w.z, z4[k].z); z4[k].w = fmaf(fv, w.w, z4[k].w);
                }
            }
            #pragma unroll
            for (int k = 0; k < 4; k++) zb[cc * 32 + k * 8 + gl] = z4[k];
            float p[9]; reduce8(z4, p);
            scorepos8(cc, p);
        }
    }
    // cols 27..53 (3 distinct groups -> W1p)
    for (int base = 0; base < 27; base += 16) {
        int cc = base + grp;
        if (cc < 27 && emptyb[cc + 27]) {
            int g0 = 3 * (cc % 3);
            float4 z4[4] = {};
            #pragma unroll
            for (int blk = 0; blk < 3; blk++) {
                const float* f = cnt[1][g0 + blk];
                #pragma unroll
                for (int e = 0; e < 9; e++) {
                    float fv = f[e];
                    #pragma unroll
                    for (int k = 0; k < 4; k++) {
                        float4 w = __ldg((const float4*)(g_W1p + (9 * blk + e) * 128) + k * 8 + gl);
                        z4[k].x = fmaf(fv, w.x, z4[k].x); z4[k].y = fmaf(fv, w.y, z4[k].y);
                        z4[k].z = fmaf(fv, w.z, z4[k].z); z4[k].w = fmaf(fv, w.w, z4[k].w);
                    }
                }
            }
            int co = cc + 27;
            #pragma unroll
            for (int k = 0; k < 4; k++) zb[co * 32 + k * 8 + gl] = z4[k];
            float p[9]; reduce8(z4, p);
            scorepos8(co, p);
        }
    }
    // boxes 54..80 (3x-replicated f -> Wsum)
    for (int base = 0; base < 27; base += 16) {
        int cc = base + grp;
        if (cc < 27 && emptyb[cc + 54]) {
            const float* f = cnt[2][3 * (cc / 9) + cc % 3];
            float4 z4[4] = {};
            #pragma unroll
            for (int e = 0; e < 9; e++) {
                float fv = f[e];
                #pragma unroll
                for (int k = 0; k < 4; k++) {
                    float4 w = __ldg((const float4*)(g_Wsum + e * 128) + k * 8 + gl);
                    z4[k].x = fmaf(fv, w.x, z4[k].x); z4[k].y = fmaf(fv, w.y, z4[k].y);
                    z4[k].z = fmaf(fv, w.z, z4[k].z); z4[k].w = fmaf(fv, w.w, z4[k].w);
                }
            }
            int co = cc + 54;
            #pragma unroll
            for (int k = 0; k < 4; k++) zb[co * 32 + k * 8 + gl] = z4[k];
            float p[9]; reduce8(z4, p);
            scorepos8(co, p);
        }
    }
    __syncthreads();

    // ---- Sequential fill loop: ONE barrier/iter; selection redundant per warp;
    //      all <=14 affected cells processed in ONE parallel pass (16 groups). ----
    for (int iter = 0; iter < 81; ++iter) {
        float s0 = score_s[lane];
        float s1 = score_s[lane + 32];
        float s2 = score_s[lane + 64];
        unsigned bb = __float_as_uint(s0); int bi = lane;
        unsigned v1 = __float_as_uint(s1); if (v1 > bb) { bb = v1; bi = lane + 32; }
        unsigned v2 = __float_as_uint(s2); if (v2 > bb) { bb = v2; bi = lane + 64; }
        unsigned wmax = redux_maxu(bb);
        if (wmax == 0u) break;              // CTA-uniform
        unsigned cand = (bb == wmax) ? (unsigned)bi : 0xFFu;
        const int m = (int)redux_minu(cand);
        const int d = pos_s[m];

        const int rm = m / 9, cm = m % 9;
        const int cm3 = cm / 3, brm = (rm / 3) * 3;

        int cl = map_cell(lane < 15 ? lane : 0, rm, cm3, brm);
        bool pr = (lane < 15) && (cl != m) && emptyb[cl];
        unsigned mask = __ballot_sync(0xffffffffu, pr);
        int ne = __popc(mask);              // <= 14 < 16 groups

        if (tid == 0) { emptyb[m] = 0; score_s[m] = 0.f; }  // read after barrier only

        if (grp < ne) {                     // group-granular divergence
            int bit = (int)__fns(mask, 0, grp + 1);
            int c   = map_cell(bit, rm, cm3, brm);
            const float* wrow = (bit >= 3 && bit < 12)
                              ? g_W1p + (9 * (cm % 3) + d) * 128
                              : g_Wsum + d * 128;
            float4 z4[4];
            #pragma unroll
            for (int k = 0; k < 4; k++) {
                float4 z = zb[c * 32 + k * 8 + gl];
                float4 w = __ldg((const float4*)wrow + k * 8 + gl);
                z.x += w.x; z.y += w.y; z.z += w.z; z.w += w.w;
                z4[k] = z;
            }
            #pragma unroll
            for (int k = 0; k < 4; k++) zb[c * 32 + k * 8 + gl] = z4[k];
            float p[9]; reduce8(z4, p);
            scorepos8(c, p);
        }

        __syncthreads();   // publish z/score/pos + m-clears to all warps
    }
    __syncthreads();

    // ---- Final pass: softmax of frozen z for initially-empty cells ----
    for (int base = 0; base < 81; base += 16) {
        int c = base + grp;
        if (c < 81 && empty0[c]) {
            float4 z4[4];
            #pragma unroll
            for (int k = 0; k < 4; k++) z4[k] = zb[c * 32 + k * 8 + gl];
            float p[9]; reduce8(z4, p);
            float mx = p[0];
            #pragma unroll
            for (int e = 1; e < 9; e++) mx = fmaxf(mx, p[e]);
            float sum = 0.f;
            #pragma unroll
            for (int e = 0; e < 9; e++) { p[e] = __expf(p[e] - mx); sum += p[e]; }
            ob[c * 9 + gl] = __fdividef(p[gl], sum);
            if (gl == 0) ob[c * 9 + 8] = __fdividef(p[8], sum);
        }
    }
}

} // namespace

extern "C" void kernel_launch(void* const* d_in, const int* in_sizes, int n_in,
                              void* d_out, int out_size) {
    const float* x  = (const float*)d_in[0];
    const float* W1 = (const float*)d_in[1];
    const float* W2 = (const float*)d_in[2];
    float* out = (float*)d_out;
    int B = in_sizes[0] / 729;
    prep_kernel<<<1, 128>>>(W1);
    sudoku_kernel<<<B, THREADS>>>(x, W2, out);
}